// round 16
// baseline (speedup 1.0000x reference)
#include <cuda_runtime.h>
#include <cuda_fp16.h>
#include <cuda.h>
#include <cstdint>
#include <cstddef>

#define CHANNELS 1024
#define PIVOT 16384

#if defined(__CUDA_ARCH_FEAT_SM103_ALL) || defined(__CUDA_ARCH_FEAT_SM100_ALL) || defined(__CUDA_ARCH_SPECIFIC__)
#define HAS_TCGEN05 1
#else
#define HAS_TCGEN05 0
#endif

// ---------------- scratch ----------------
__device__ __align__(1024) __half Xh_g[(size_t)PIVOT * CHANNELS];        // 32 MB
__device__ __align__(1024) __half Wh_g[(size_t)CHANNELS * CHANNELS];     //  2 MB
__device__ __align__(1024) __half A2_g[(size_t)2 * PIVOT * CHANNELS];    // 64 MB

// ---------------- device helpers ----------------
__device__ __forceinline__ uint32_t smem_u32(const void* p) {
    uint32_t r;
    asm("{ .reg .u64 t; cvta.to.shared.u64 t, %1; cvt.u32.u64 %0, t; }" : "=r"(r) : "l"(p));
    return r;
}
__device__ __forceinline__ uint32_t elect_one() {
    uint32_t p;
    asm volatile("{ .reg .pred p; elect.sync _|p, 0xFFFFFFFF; selp.b32 %0, 1, 0, p; }" : "=r"(p));
    return p;
}
// SW128 K-major smem descriptor (layout=2, version=1, SBO=64, LBO=1)
__device__ __forceinline__ uint64_t make_desc(uint32_t addr) {
    const uint64_t base = (uint64_t(2) << 61) | (uint64_t(1) << 46)
                        | (uint64_t(64) << 32) | (uint64_t(1) << 16);
    return base | ((uint64_t)(addr >> 4) & 0x3FFF);
}

#if HAS_TCGEN05
__device__ __forceinline__ uint32_t ctarank() {
    uint32_t r; asm("mov.u32 %0, %%cluster_ctarank;" : "=r"(r)); return r;
}
#define TCG_ALLOC_CG2(smem_res, ncols) \
    asm volatile("tcgen05.alloc.cta_group::2.sync.aligned.shared::cta.b32 [%0], %1;" \
                 :: "r"(smem_res), "r"((uint32_t)(ncols)) : "memory")
#define TCG_DEALLOC_CG2(tmem, ncols) \
    asm volatile("tcgen05.dealloc.cta_group::2.sync.aligned.b32 %0, %1;" \
                 :: "r"(tmem), "r"((uint32_t)(ncols)))
#define TCG_RELINQ_CG2() \
    asm volatile("tcgen05.relinquish_alloc_permit.cta_group::2.sync.aligned;")
#define TCG_COMMIT_MC2(mbar) \
    asm volatile("tcgen05.commit.cta_group::2.mbarrier::arrive::one.shared::cluster.multicast::cluster.b64 [%0], %1;" \
                 :: "r"(mbar), "h"((uint16_t)3) : "memory")
#define TCG_FENCE_AFTER()  asm volatile("tcgen05.fence::after_thread_sync;" ::: "memory")
#define TCG_FENCE_BEFORE() asm volatile("tcgen05.fence::before_thread_sync;" ::: "memory")
#define TCG_WAIT_LD()      asm volatile("tcgen05.wait::ld.sync.aligned;" ::: "memory")
#define FENCE_ASYNC()      asm volatile("fence.proxy.async.shared::cta;" ::: "memory")
#define MBAR_INIT(addr, cnt) \
    asm volatile("mbarrier.init.shared.b64 [%0], %1;" :: "r"(addr), "r"((uint32_t)(cnt)) : "memory")
#define MBAR_INVAL(addr) \
    asm volatile("mbarrier.inval.shared.b64 [%0];" :: "r"(addr) : "memory")
#define MBAR_EXPECT_TX(addr, bytes) \
    asm volatile("mbarrier.arrive.expect_tx.shared.b64 _, [%0], %1;" \
                 :: "r"(addr), "r"((uint32_t)(bytes)) : "memory")
#define CLUSTER_SYNC() do { \
    asm volatile("barrier.cluster.arrive.aligned;" ::: "memory"); \
    asm volatile("barrier.cluster.wait.aligned;"   ::: "memory"); } while (0)

// Sleep-hint wait (HW TRYWAIT)
__device__ __forceinline__ void mbar_wait(uint32_t addr, uint32_t parity) {
    asm volatile(
        "{\n\t.reg .pred P;\n\t"
        "W_%=:\n\t"
        "mbarrier.try_wait.parity.shared.b64 P, [%0], %1, 0x989680;\n\t"
        "@!P bra W_%=;\n\t}"
        :: "r"(addr), "r"(parity) : "memory");
}
__device__ __forceinline__ void mbar_wait_acq(uint32_t addr, uint32_t parity) {
    asm volatile(
        "{\n\t.reg .pred P;\n\t"
        "W_%=:\n\t"
        "mbarrier.try_wait.parity.acquire.cluster.shared::cta.b64 P, [%0], %1, 0x989680;\n\t"
        "@!P bra W_%=;\n\t}"
        :: "r"(addr), "r"(parity) : "memory");
}
// release-arrive on leader CTA (rank 0) at same smem offset
__device__ __forceinline__ void arrive_leader(uint32_t addr) {
    asm volatile(
        "{\n\t.reg .b32 ra;\n\t"
        "mapa.shared::cluster.u32 ra, %0, 0;\n\t"
        "mbarrier.arrive.release.cluster.shared::cluster.b64 _, [ra];\n\t}"
        :: "r"(addr) : "memory");
}
__device__ __forceinline__ void tma2d(uint32_t dst, const void* map,
                                      int32_t cx, int32_t cy, uint32_t mbar) {
    asm volatile(
        "cp.async.bulk.tensor.2d.shared::cta.global.tile.mbarrier::complete_tx::bytes "
        "[%0], [%1, {%2, %3}], [%4];"
        :: "r"(dst), "l"(map), "r"(cx), "r"(cy), "r"(mbar) : "memory");
}
__device__ __forceinline__ void mma_f16_cg2(uint32_t d_tmem, uint64_t a_desc,
                                            uint64_t b_desc, uint32_t idesc, uint32_t en) {
    asm volatile(
        "{\n\t.reg .pred p;\n\t"
        "setp.ne.u32 p, %4, 0;\n\t"
        "tcgen05.mma.cta_group::2.kind::f16 [%0], %1, %2, %3, {%5,%5,%5,%5,%5,%5,%5,%5}, p;\n\t}"
        :: "r"(d_tmem), "l"(a_desc), "l"(b_desc), "r"(idesc), "r"(en), "r"(0u) : "memory");
}
#define TCG_LD_X32(r, addr) \
    asm volatile( \
        "tcgen05.ld.sync.aligned.32x32b.x32.b32 " \
        "{%0, %1, %2, %3, %4, %5, %6, %7, " \
        " %8, %9, %10, %11, %12, %13, %14, %15, " \
        " %16, %17, %18, %19, %20, %21, %22, %23, " \
        " %24, %25, %26, %27, %28, %29, %30, %31}, [%32];" \
        : "=r"((r)[0]),  "=r"((r)[1]),  "=r"((r)[2]),  "=r"((r)[3]), \
          "=r"((r)[4]),  "=r"((r)[5]),  "=r"((r)[6]),  "=r"((r)[7]), \
          "=r"((r)[8]),  "=r"((r)[9]),  "=r"((r)[10]), "=r"((r)[11]), \
          "=r"((r)[12]), "=r"((r)[13]), "=r"((r)[14]), "=r"((r)[15]), \
          "=r"((r)[16]), "=r"((r)[17]), "=r"((r)[18]), "=r"((r)[19]), \
          "=r"((r)[20]), "=r"((r)[21]), "=r"((r)[22]), "=r"((r)[23]), \
          "=r"((r)[24]), "=r"((r)[25]), "=r"((r)[26]), "=r"((r)[27]), \
          "=r"((r)[28]), "=r"((r)[29]), "=r"((r)[30]), "=r"((r)[31]) \
        : "r"(addr))
#endif  // HAS_TCGEN05

// ---------------- convert kernels ----------------
__global__ void cvt_XW(const float* __restrict__ X, const float* __restrict__ W) {
    const size_t NX = (size_t)PIVOT * CHANNELS / 4;
    const size_t NW = (size_t)CHANNELS * CHANNELS / 4;
    size_t i = (size_t)blockIdx.x * blockDim.x + threadIdx.x;
    if (i < NX) {
        float4 f = reinterpret_cast<const float4*>(X)[i];
        __half2* o = reinterpret_cast<__half2*>(Xh_g) + i * 2;
        o[0] = __floats2half2_rn(f.x, f.y);
        o[1] = __floats2half2_rn(f.z, f.w);
    } else if (i < NX + NW) {
        size_t j = i - NX;
        float4 f = reinterpret_cast<const float4*>(W)[j];
        __half2* o = reinterpret_cast<__half2*>(Wh_g) + j * 2;
        o[0] = __floats2half2_rn(f.x, f.y);
        o[1] = __floats2half2_rn(f.z, f.w);
    }
}
// Deinterleave J: A2[2p+k][j] = J[p][2j+k]
__global__ void cvt_J(const float* __restrict__ J) {
    size_t i = (size_t)blockIdx.x * blockDim.x + threadIdx.x;  // float4 index
    size_t p = i >> 9, q = i & 511;
    float4 f = reinterpret_cast<const float4*>(J)[i];
    reinterpret_cast<__half2*>(A2_g + (2 * p) * CHANNELS)[q]     = __floats2half2_rn(f.x, f.z);
    reinterpret_cast<__half2*>(A2_g + (2 * p + 1) * CHANNELS)[q] = __floats2half2_rn(f.y, f.w);
}

// -------- cg2 pair-tile TMA tcgen05 GEMM: 256(M) x 512(N) x 64, 3 stages --------
// Each CTA per kt: A-half 16KB (its 128 M-rows) + two B chunks (its 128 N-rows
// of each 256-col group) = 48KB for a 2x larger tile than R14.
#define BMP 256
#define BN2 512
#define BK 64
#define ST 3
#define KT (CHANNELS / BK)                   // 16
#define STAGE_B 49152                        // A 16KB + B 32KB
#define STAGES0 4096
#define SMEM_TOTAL (STAGES0 + ST * STAGE_B)  // 151552
// cg2 idesc: f32 acc, f16 a/b, N=256 per MMA, M=256 (pair)
#define IDESC2 ((1u << 4) | (32u << 17) | (16u << 24))
// ctrl smem: [0,4) tmem ptr; full[s] @ 16+8s (leader cnt 2 / follower cnt 1);
//            done[s] @ 48+8s (cnt 1, MC'd); fin @ 80 (cnt 1, MC'd); bias @ 1024

template<int EPI>
__global__ void __launch_bounds__(256, 1) __cluster_dims__(2, 1, 1)
gemm_cg2(const __grid_constant__ CUtensorMap mapA,   // box {64,128}
         const __grid_constant__ CUtensorMap mapB,   // box {64,128}
         const __half* __restrict__ Araw, const __half* __restrict__ Wraw,
         const float* __restrict__ aux,   // EPI0: bias; EPI1: h = out[0:PIVOT]
         float* __restrict__ outp)        // EPI0: out;  EPI1: out2
{
#if HAS_TCGEN05
    extern __shared__ char smem[];
    const uint32_t sbase = smem_u32(smem);
    const int tid = threadIdx.x, wid = tid >> 5, lane = tid & 31;
    const uint32_t rank = ctarank();
    const int n0 = (int)(blockIdx.x >> 1) * BN2;
    const int m0 = blockIdx.y * BMP;

    if (wid == 7) TCG_ALLOC_CG2(sbase, 512);
    if (tid == 0) {
        #pragma unroll
        for (int s = 0; s < ST; s++) {
            MBAR_INIT(sbase + 16 + 8 * s, (rank == 0) ? 2u : 1u);   // full
            MBAR_INIT(sbase + 48 + 8 * s, 1u);                      // done
        }
        MBAR_INIT(sbase + 80, 1u);                                  // fin
    }
    __syncthreads();
    uint32_t tmem;
    asm volatile("ld.shared.b32 %0, [%1];" : "=r"(tmem) : "r"(sbase));
    CLUSTER_SYNC();   // barriers live before any remote arrive / MC commit

    auto issue = [&](int kt) {
        const int s = kt % ST;
        const uint32_t stg = sbase + STAGES0 + s * STAGE_B;
        const uint32_t fb  = sbase + 16 + 8 * s;
        const int k0 = kt * BK;
        MBAR_EXPECT_TX(fb, STAGE_B);   // 48KB local tx
        tma2d(stg,         &mapA, k0, m0 + 128 * (int)rank, fb);
        tma2d(stg + 16384, &mapB, k0, n0 + 128 * (int)rank, fb);
        tma2d(stg + 32768, &mapB, k0, n0 + 256 + 128 * (int)rank, fb);
    };

    if (wid == 6 && lane == 0) {
        if (rank == 1) {
            // -------- follower producer: fill, signal leader, reuse-gate --------
            issue(0); issue(1); issue(2);
            #pragma unroll 1
            for (int kt = 0; kt < KT; kt++) {
                const int s = kt % ST;
                mbar_wait(sbase + 16 + 8 * s, (uint32_t)((kt / ST) & 1));  // own tx done
                arrive_leader(sbase + 16 + 8 * s);                          // release to leader
                if (kt + 3 < KT) {
                    mbar_wait(sbase + 48 + 8 * s, (uint32_t)((kt / ST) & 1));
                    issue(kt + 3);
                }
            }
        } else {
            // -------- leader producer --------
            issue(0); issue(1); issue(2);
            #pragma unroll 1
            for (int kt = 0; kt + 3 < KT; kt++) {
                mbar_wait(sbase + 48 + 8 * (kt % ST), (uint32_t)((kt / ST) & 1));
                issue(kt + 3);
            }
        }
    } else if (wid == 7 && rank == 0) {
        // -------- MMA warp (leader only) --------
        #pragma unroll 1
        for (int kt = 0; kt < KT; kt++) {
            const int s = kt % ST;
            mbar_wait_acq(sbase + 16 + 8 * s, (uint32_t)((kt / ST) & 1));
            if (elect_one()) {
                const uint32_t stg = sbase + STAGES0 + s * STAGE_B;
                uint64_t ad  = make_desc(stg);
                uint64_t bd0 = make_desc(stg + 16384);
                uint64_t bd1 = make_desc(stg + 32768);
                #pragma unroll
                for (int ks = 0; ks < 4; ks++) {
                    uint32_t en = (kt > 0 || ks > 0) ? 1u : 0u;
                    mma_f16_cg2(tmem,       ad + 2 * ks, bd0 + 2 * ks, IDESC2, en);
                    mma_f16_cg2(tmem + 256, ad + 2 * ks, bd1 + 2 * ks, IDESC2, en);
                }
                TCG_COMMIT_MC2((kt < KT - 1) ? (sbase + 48 + 8 * s) : (sbase + 80));
            }
        }
    }

    // -------- all threads: wait for final MMA (dedicated fin, single flip) --------
    mbar_wait(sbase + 80, 0);
    TCG_FENCE_AFTER();
    FENCE_ASYNC();
    __syncthreads();

    const int cg = wid >> 2, sub = wid & 3;       // cg: column group (0/1)

    if (EPI == 0) {
        float* bs = reinterpret_cast<float*>(smem + 1024);   // 512 floats
        bs[tid] = aux[n0 + tid];
        bs[256 + tid] = aux[n0 + 256 + tid];
        __syncthreads();
        const int row = m0 + 128 * (int)rank + sub * 32 + lane;
        const int cb = cg * 256;
        #pragma unroll 1
        for (int cc = 0; cc < 8; cc++) {
            uint32_t d[32];
            TCG_LD_X32(d, tmem + cb + cc * 32);
            TCG_WAIT_LD();
            float* orow = outp + (size_t)row * CHANNELS + n0 + cb + cc * 32;
            #pragma unroll
            for (int j = 0; j < 32; j += 4) {
                float4 o;
                o.x = tanhf(__uint_as_float(d[j + 0]) + bs[cb + cc * 32 + j + 0]);
                o.y = tanhf(__uint_as_float(d[j + 1]) + bs[cb + cc * 32 + j + 1]);
                o.z = tanhf(__uint_as_float(d[j + 2]) + bs[cb + cc * 32 + j + 2]);
                o.w = tanhf(__uint_as_float(d[j + 3]) + bs[cb + cc * 32 + j + 3]);
                *reinterpret_cast<float4*>(orow + j) = o;
            }
        }
    } else {
        // Transposed coalesced epilogue: two passes over 256-col groups.
        float* rs = reinterpret_cast<float*>(smem + STAGES0);   // 128 x 257 floats
        const int pb = (m0 + 128 * (int)rank) >> 1;             // 64 p-rows
        #pragma unroll 1
        for (int cp = 0; cp < 2; cp++) {
            if (cg == cp) {
                const int vl = sub * 32 + lane;                  // 0..127
                #pragma unroll 1
                for (int cc = 0; cc < 8; cc++) {
                    uint32_t d[32];
                    TCG_LD_X32(d, tmem + cp * 256 + cc * 32);
                    TCG_WAIT_LD();
                    #pragma unroll
                    for (int j = 0; j < 32; j++)
                        rs[vl * 257 + cc * 32 + j] = __uint_as_float(d[j]);
                }
            }
            __syncthreads();
            #pragma unroll 1
            for (int r8 = 0; r8 < 8; r8++) {
                const int pr = wid * 8 + r8;                     // 0..63
                const float* hrow = aux + (size_t)(pb + pr) * CHANNELS + n0 + 256 * cp;
                float* orow = outp + (size_t)(pb + pr) * 2048 + 2 * (size_t)(n0 + 256 * cp);
                const float* r0 = rs + (2 * pr) * 257;
                const float* r1 = r0 + 257;
                #pragma unroll
                for (int c = 0; c < 4; c++) {
                    const int i0 = 64 * c + 2 * lane;
                    float2 hv = *reinterpret_cast<const float2*>(hrow + i0);
                    float g0 = 1.f - hv.x * hv.x;
                    float g1 = 1.f - hv.y * hv.y;
                    float4 o;
                    o.x = g0 * r0[i0];
                    o.y = g0 * r1[i0];
                    o.z = g1 * r0[i0 + 1];
                    o.w = g1 * r1[i0 + 1];
                    *reinterpret_cast<float4*>(orow + 4 * (32 * c + lane)) = o;
                }
            }
            __syncthreads();
        }
    }

    TCG_FENCE_BEFORE();
    __syncthreads();
    CLUSTER_SYNC();   // all remote arrives / MC commits into my smem landed
    if (tid == 0) {
        #pragma unroll
        for (int s = 0; s < ST; s++) { MBAR_INVAL(sbase + 16 + 8 * s); MBAR_INVAL(sbase + 48 + 8 * s); }
        MBAR_INVAL(sbase + 80);
    }
    __syncthreads();
    if (wid == 7) { TCG_RELINQ_CG2(); TCG_DEALLOC_CG2(tmem, 512); }
    CLUSTER_SYNC();

#else  // ---------- non-sm_103a fallback (never runs on GB300) ----------
    const int tid = threadIdx.x;
    const int rank = (int)(blockIdx.x & 1);
    const int n0 = (int)(blockIdx.x >> 1) * BN2;
    const int m0 = blockIdx.y * BMP + 128 * rank;
    for (int idx = tid; idx < 128 * BN2; idx += blockDim.x) {
        int mi = idx >> 9, ni = idx & 511;
        int m = m0 + mi, n = n0 + ni;
        float acc = 0.f;
        for (int k = 0; k < CHANNELS; k++)
            acc += __half2float(Araw[(size_t)m * CHANNELS + k]) *
                   __half2float(Wraw[(size_t)n * CHANNELS + k]);
        if (EPI == 0) {
            outp[(size_t)m * CHANNELS + n] = tanhf(acc + aux[n]);
        } else {
            int p = m >> 1, kb = m & 1;
            float hv = aux[(size_t)p * CHANNELS + n];
            outp[(size_t)p * 2048 + 2 * (size_t)n + kb] = (1.f - hv * hv) * acc;
        }
    }
#endif
}

// ---------------- host launcher ----------------
typedef CUresult (*tmap_encode_fn)(
    CUtensorMap*, CUtensorMapDataType, cuuint32_t, void*,
    const cuuint64_t*, const cuuint64_t*, const cuuint32_t*, const cuuint32_t*,
    CUtensorMapInterleave, CUtensorMapSwizzle, CUtensorMapL2promotion,
    CUtensorMapFloatOOBfill);

static void make_map2d(tmap_encode_fn enc, CUtensorMap* m, void* base,
                       unsigned long long rows) {
    cuuint64_t dims[2]    = {(cuuint64_t)CHANNELS, (cuuint64_t)rows};
    cuuint64_t strides[1] = {(cuuint64_t)(CHANNELS * sizeof(__half))};
    cuuint32_t box[2]     = {64u, 128u};
    cuuint32_t es[2]      = {1u, 1u};
    enc(m, CU_TENSOR_MAP_DATA_TYPE_FLOAT16, 2, base, dims, strides, box, es,
        CU_TENSOR_MAP_INTERLEAVE_NONE, CU_TENSOR_MAP_SWIZZLE_128B,
        CU_TENSOR_MAP_L2_PROMOTION_L2_128B, CU_TENSOR_MAP_FLOAT_OOB_FILL_NONE);
}

extern "C" void kernel_launch(void* const* d_in, const int* in_sizes, int n_in,
                              void* d_out, int out_size)
{
    const float* x = (const float*)d_in[0];   // [3*PIVOT, CHANNELS]
    const float* W = (const float*)d_in[1];   // [CHANNELS, CHANNELS]
    const float* b = (const float*)d_in[2];   // [CHANNELS]
    float* out = (float*)d_out;

    void *pX = nullptr, *pW = nullptr, *pA2 = nullptr;
    cudaGetSymbolAddress(&pX,  Xh_g);
    cudaGetSymbolAddress(&pW,  Wh_g);
    cudaGetSymbolAddress(&pA2, A2_g);

    void* encp = nullptr;
    cudaDriverEntryPointQueryResult qr;
    cudaGetDriverEntryPoint("cuTensorMapEncodeTiled", &encp, cudaEnableDefault, &qr);
    tmap_encode_fn enc = (tmap_encode_fn)encp;

    CUtensorMap mX, mW, mA2;
    make_map2d(enc, &mX,  pX,  PIVOT);
    make_map2d(enc, &mW,  pW,  CHANNELS);
    make_map2d(enc, &mA2, pA2, 2 * PIVOT);

    cudaFuncSetAttribute(gemm_cg2<0>, cudaFuncAttributeMaxDynamicSharedMemorySize, SMEM_TOTAL);
    cudaFuncSetAttribute(gemm_cg2<1>, cudaFuncAttributeMaxDynamicSharedMemorySize, SMEM_TOTAL);

    const size_t NX = (size_t)PIVOT * CHANNELS / 4;
    const size_t NW = (size_t)CHANNELS * CHANNELS / 4;
    cvt_XW<<<(unsigned)((NX + NW) / 256), 256>>>(x, W);
    cvt_J<<<(unsigned)((size_t)PIVOT * 512 / 256), 256>>>(x + (size_t)PIVOT * CHANNELS);

    // gridx = 2 n-tiles x 2 ranks = 4
    dim3 g1(4, PIVOT / BMP);                 // (4, 64)  = 256 CTAs (128 pairs)
    gemm_cg2<0><<<g1, 256, SMEM_TOTAL>>>(mX, mW, (const __half*)pX, (const __half*)pW, b, out);

    dim3 g2(4, (2 * PIVOT) / BMP);           // (4, 128) = 512 CTAs (256 pairs)
    gemm_cg2<1><<<g2, 256, SMEM_TOTAL>>>(mA2, mW, (const __half*)pA2, (const __half*)pW,
                                         out, out + (size_t)PIVOT * CHANNELS);
}

// round 17
// speedup vs baseline: 1.3632x; 1.3632x over previous
#include <cuda_runtime.h>
#include <cuda_fp16.h>
#include <cuda.h>
#include <cstdint>
#include <cstddef>

#define CHANNELS 1024
#define PIVOT 16384

#if defined(__CUDA_ARCH_FEAT_SM103_ALL) || defined(__CUDA_ARCH_FEAT_SM100_ALL) || defined(__CUDA_ARCH_SPECIFIC__)
#define HAS_TCGEN05 1
#else
#define HAS_TCGEN05 0
#endif

// ---------------- scratch ----------------
__device__ __align__(1024) __half Xh_g[(size_t)PIVOT * CHANNELS];        // 32 MB
__device__ __align__(1024) __half Wh_g[(size_t)CHANNELS * CHANNELS];     //  2 MB
__device__ __align__(1024) __half A2_g[(size_t)2 * PIVOT * CHANNELS];    // 64 MB

// ---------------- device helpers ----------------
__device__ __forceinline__ uint32_t smem_u32(const void* p) {
    uint32_t r;
    asm("{ .reg .u64 t; cvta.to.shared.u64 t, %1; cvt.u32.u64 %0, t; }" : "=r"(r) : "l"(p));
    return r;
}
__device__ __forceinline__ uint32_t elect_one() {
    uint32_t p;
    asm volatile("{ .reg .pred p; elect.sync _|p, 0xFFFFFFFF; selp.b32 %0, 1, 0, p; }" : "=r"(p));
    return p;
}
// SW128 K-major smem descriptor (layout=2, version=1, SBO=64, LBO=1)
__device__ __forceinline__ uint64_t make_desc(uint32_t addr) {
    const uint64_t base = (uint64_t(2) << 61) | (uint64_t(1) << 46)
                        | (uint64_t(64) << 32) | (uint64_t(1) << 16);
    return base | ((uint64_t)(addr >> 4) & 0x3FFF);
}

#if HAS_TCGEN05
__device__ __forceinline__ uint32_t ctarank() {
    uint32_t r; asm("mov.u32 %0, %%cluster_ctarank;" : "=r"(r)); return r;
}
#define TCG_ALLOC_CG2(smem_res, ncols) \
    asm volatile("tcgen05.alloc.cta_group::2.sync.aligned.shared::cta.b32 [%0], %1;" \
                 :: "r"(smem_res), "r"((uint32_t)(ncols)) : "memory")
#define TCG_DEALLOC_CG2(tmem, ncols) \
    asm volatile("tcgen05.dealloc.cta_group::2.sync.aligned.b32 %0, %1;" \
                 :: "r"(tmem), "r"((uint32_t)(ncols)))
#define TCG_RELINQ_CG2() \
    asm volatile("tcgen05.relinquish_alloc_permit.cta_group::2.sync.aligned;")
#define TCG_COMMIT_MC2(mbar) \
    asm volatile("tcgen05.commit.cta_group::2.mbarrier::arrive::one.shared::cluster.multicast::cluster.b64 [%0], %1;" \
                 :: "r"(mbar), "h"((uint16_t)3) : "memory")
#define TCG_FENCE_AFTER()  asm volatile("tcgen05.fence::after_thread_sync;" ::: "memory")
#define TCG_FENCE_BEFORE() asm volatile("tcgen05.fence::before_thread_sync;" ::: "memory")
#define TCG_WAIT_LD()      asm volatile("tcgen05.wait::ld.sync.aligned;" ::: "memory")
#define FENCE_ASYNC()      asm volatile("fence.proxy.async.shared::cta;" ::: "memory")
#define MBAR_INIT(addr, cnt) \
    asm volatile("mbarrier.init.shared.b64 [%0], %1;" :: "r"(addr), "r"((uint32_t)(cnt)) : "memory")
#define MBAR_INVAL(addr) \
    asm volatile("mbarrier.inval.shared.b64 [%0];" :: "r"(addr) : "memory")
#define MBAR_EXPECT_TX(addr, bytes) \
    asm volatile("mbarrier.arrive.expect_tx.shared.b64 _, [%0], %1;" \
                 :: "r"(addr), "r"((uint32_t)(bytes)) : "memory")
#define CLUSTER_SYNC() do { \
    asm volatile("barrier.cluster.arrive.aligned;" ::: "memory"); \
    asm volatile("barrier.cluster.wait.aligned;"   ::: "memory"); } while (0)

// Sleep-hint wait (HW TRYWAIT)
__device__ __forceinline__ void mbar_wait(uint32_t addr, uint32_t parity) {
    asm volatile(
        "{\n\t.reg .pred P;\n\t"
        "W_%=:\n\t"
        "mbarrier.try_wait.parity.shared.b64 P, [%0], %1, 0x989680;\n\t"
        "@!P bra W_%=;\n\t}"
        :: "r"(addr), "r"(parity) : "memory");
}
// cta_group::2 2D TMA load: both CTAs execute; data lands in each CTA's own
// smem; complete_tx targets the LEADER CTA's barrier (bit 24 cleared).
__device__ __forceinline__ void tma2d_cg2(uint32_t dst, const void* map,
                                          int32_t cx, int32_t cy, uint32_t mbar) {
    asm volatile(
        "{\n\t.reg .b32 lb;\n\t"
        "and.b32 lb, %4, 0xFEFFFFFF;\n\t"
        "cp.async.bulk.tensor.2d.cta_group::2.shared::cluster.global.tile.mbarrier::complete_tx::bytes "
        "[%0], [%1, {%2, %3}], [lb];\n\t}"
        :: "r"(dst), "l"(map), "r"(cx), "r"(cy), "r"(mbar) : "memory");
}
__device__ __forceinline__ void mma_f16_cg2(uint32_t d_tmem, uint64_t a_desc,
                                            uint64_t b_desc, uint32_t idesc, uint32_t en) {
    asm volatile(
        "{\n\t.reg .pred p;\n\t"
        "setp.ne.u32 p, %4, 0;\n\t"
        "tcgen05.mma.cta_group::2.kind::f16 [%0], %1, %2, %3, {%5,%5,%5,%5,%5,%5,%5,%5}, p;\n\t}"
        :: "r"(d_tmem), "l"(a_desc), "l"(b_desc), "r"(idesc), "r"(en), "r"(0u) : "memory");
}
#define TCG_LD_X32(r, addr) \
    asm volatile( \
        "tcgen05.ld.sync.aligned.32x32b.x32.b32 " \
        "{%0, %1, %2, %3, %4, %5, %6, %7, " \
        " %8, %9, %10, %11, %12, %13, %14, %15, " \
        " %16, %17, %18, %19, %20, %21, %22, %23, " \
        " %24, %25, %26, %27, %28, %29, %30, %31}, [%32];" \
        : "=r"((r)[0]),  "=r"((r)[1]),  "=r"((r)[2]),  "=r"((r)[3]), \
          "=r"((r)[4]),  "=r"((r)[5]),  "=r"((r)[6]),  "=r"((r)[7]), \
          "=r"((r)[8]),  "=r"((r)[9]),  "=r"((r)[10]), "=r"((r)[11]), \
          "=r"((r)[12]), "=r"((r)[13]), "=r"((r)[14]), "=r"((r)[15]), \
          "=r"((r)[16]), "=r"((r)[17]), "=r"((r)[18]), "=r"((r)[19]), \
          "=r"((r)[20]), "=r"((r)[21]), "=r"((r)[22]), "=r"((r)[23]), \
          "=r"((r)[24]), "=r"((r)[25]), "=r"((r)[26]), "=r"((r)[27]), \
          "=r"((r)[28]), "=r"((r)[29]), "=r"((r)[30]), "=r"((r)[31]) \
        : "r"(addr))
#endif  // HAS_TCGEN05

// ---------------- convert kernels ----------------
__global__ void cvt_XW(const float* __restrict__ X, const float* __restrict__ W) {
    const size_t NX = (size_t)PIVOT * CHANNELS / 4;
    const size_t NW = (size_t)CHANNELS * CHANNELS / 4;
    size_t i = (size_t)blockIdx.x * blockDim.x + threadIdx.x;
    if (i < NX) {
        float4 f = reinterpret_cast<const float4*>(X)[i];
        __half2* o = reinterpret_cast<__half2*>(Xh_g) + i * 2;
        o[0] = __floats2half2_rn(f.x, f.y);
        o[1] = __floats2half2_rn(f.z, f.w);
    } else if (i < NX + NW) {
        size_t j = i - NX;
        float4 f = reinterpret_cast<const float4*>(W)[j];
        __half2* o = reinterpret_cast<__half2*>(Wh_g) + j * 2;
        o[0] = __floats2half2_rn(f.x, f.y);
        o[1] = __floats2half2_rn(f.z, f.w);
    }
}
// Deinterleave J: A2[2p+k][j] = J[p][2j+k]
__global__ void cvt_J(const float* __restrict__ J) {
    size_t i = (size_t)blockIdx.x * blockDim.x + threadIdx.x;  // float4 index
    size_t p = i >> 9, q = i & 511;
    float4 f = reinterpret_cast<const float4*>(J)[i];
    reinterpret_cast<__half2*>(A2_g + (2 * p) * CHANNELS)[q]     = __floats2half2_rn(f.x, f.z);
    reinterpret_cast<__half2*>(A2_g + (2 * p + 1) * CHANNELS)[q] = __floats2half2_rn(f.y, f.w);
}

// ---- cg2 pair-tile GEMM with cta_group::2 TMA: 256(M) x 512(N) x 64, 3 stages ----
// Per CTA per kt: A-half 16KB + two 128-row B chunks 32KB = 48KB (vs 64KB at R14)
// for a 2x larger pair tile. All TMA completions land on the LEADER's full[s]
// (count 1, expect_tx 96KB) -> no per-kt cross-CTA handshake at all.
#define BMP 256
#define BN2 512
#define BK 64
#define ST 3
#define KT (CHANNELS / BK)                   // 16
#define STAGE_B 49152                        // A 16KB + B 32KB per CTA
#define STAGES0 4096
#define SMEM_TOTAL (STAGES0 + ST * STAGE_B)  // 151552
#define IDESC2 ((1u << 4) | (32u << 17) | (16u << 24))   // f32 acc, f16, N=256, M=256
// ctrl smem: [0,4) tmem ptr; full[s] @ 16+8s (leader: cnt 1, tx 96KB);
//            done[s] @ 48+8s (cnt 1, MC'd); fin @ 80 (cnt 1, MC'd); bias @ 1024

template<int EPI>
__global__ void __launch_bounds__(256, 1) __cluster_dims__(2, 1, 1)
gemm_cg2(const __grid_constant__ CUtensorMap mapA,   // box {64,128}
         const __grid_constant__ CUtensorMap mapB,   // box {64,128}
         const __half* __restrict__ Araw, const __half* __restrict__ Wraw,
         const float* __restrict__ aux,   // EPI0: bias; EPI1: h = out[0:PIVOT]
         float* __restrict__ outp)        // EPI0: out;  EPI1: out2
{
#if HAS_TCGEN05
    extern __shared__ char smem[];
    const uint32_t sbase = smem_u32(smem);
    const int tid = threadIdx.x, wid = tid >> 5, lane = tid & 31;
    const uint32_t rank = ctarank();
    const int n0 = (int)(blockIdx.x >> 1) * BN2;
    const int m0 = blockIdx.y * BMP;

    if (wid == 7) TCG_ALLOC_CG2(sbase, 512);
    if (tid == 0) {
        #pragma unroll
        for (int s = 0; s < ST; s++) {
            MBAR_INIT(sbase + 16 + 8 * s, 1u);   // full (used on leader only)
            MBAR_INIT(sbase + 48 + 8 * s, 1u);   // done (MC'd to both)
        }
        MBAR_INIT(sbase + 80, 1u);               // fin (MC'd to both)
    }
    __syncthreads();
    uint32_t tmem;
    asm volatile("ld.shared.b32 %0, [%1];" : "=r"(tmem) : "r"(sbase));
    CLUSTER_SYNC();   // leader's barriers live before any cg2-TMA completion

    // Both ranks run the SAME decoupled producer loop.
    auto issue = [&](int kt) {
        const int s = kt % ST;
        const uint32_t stg = sbase + STAGES0 + s * STAGE_B;
        const uint32_t fb  = sbase + 16 + 8 * s;
        const int k0 = kt * BK;
        if (rank == 0) MBAR_EXPECT_TX(fb, 2 * STAGE_B);   // 96KB total, leader barrier
        tma2d_cg2(stg,         &mapA, k0, m0 + 128 * (int)rank, fb);
        tma2d_cg2(stg + 16384, &mapB, k0, n0 + 128 * (int)rank, fb);
        tma2d_cg2(stg + 32768, &mapB, k0, n0 + 256 + 128 * (int)rank, fb);
    };

    if (wid == 6 && lane == 0) {
        issue(0); issue(1); issue(2);
        #pragma unroll 1
        for (int kt = 0; kt + 3 < KT; kt++) {
            mbar_wait(sbase + 48 + 8 * (kt % ST), (uint32_t)((kt / ST) & 1));
            issue(kt + 3);
        }
    } else if (wid == 7 && rank == 0) {
        // -------- MMA warp (leader only) --------
        #pragma unroll 1
        for (int kt = 0; kt < KT; kt++) {
            const int s = kt % ST;
            mbar_wait(sbase + 16 + 8 * s, (uint32_t)((kt / ST) & 1));
            if (elect_one()) {
                const uint32_t stg = sbase + STAGES0 + s * STAGE_B;
                uint64_t ad  = make_desc(stg);
                uint64_t bd0 = make_desc(stg + 16384);
                uint64_t bd1 = make_desc(stg + 32768);
                #pragma unroll
                for (int ks = 0; ks < 4; ks++) {
                    uint32_t en = (kt > 0 || ks > 0) ? 1u : 0u;
                    mma_f16_cg2(tmem,       ad + 2 * ks, bd0 + 2 * ks, IDESC2, en);
                    mma_f16_cg2(tmem + 256, ad + 2 * ks, bd1 + 2 * ks, IDESC2, en);
                }
                TCG_COMMIT_MC2((kt < KT - 1) ? (sbase + 48 + 8 * s) : (sbase + 80));
            }
        }
    }

    // -------- all threads: wait for final MMA --------
    mbar_wait(sbase + 80, 0);
    TCG_FENCE_AFTER();
    FENCE_ASYNC();
    __syncthreads();

    const int cg = wid >> 2, sub = wid & 3;       // cg: 256-col group (0/1)

    if (EPI == 0) {
        float* bs = reinterpret_cast<float*>(smem + 1024);   // 512 floats
        bs[tid] = aux[n0 + tid];
        bs[256 + tid] = aux[n0 + 256 + tid];
        __syncthreads();
        const int row = m0 + 128 * (int)rank + sub * 32 + lane;
        const int cb = cg * 256;
        #pragma unroll 1
        for (int cc = 0; cc < 8; cc++) {
            uint32_t d[32];
            TCG_LD_X32(d, tmem + cb + cc * 32);
            TCG_WAIT_LD();
            float* orow = outp + (size_t)row * CHANNELS + n0 + cb + cc * 32;
            #pragma unroll
            for (int j = 0; j < 32; j += 4) {
                float4 o;
                o.x = tanhf(__uint_as_float(d[j + 0]) + bs[cb + cc * 32 + j + 0]);
                o.y = tanhf(__uint_as_float(d[j + 1]) + bs[cb + cc * 32 + j + 1]);
                o.z = tanhf(__uint_as_float(d[j + 2]) + bs[cb + cc * 32 + j + 2]);
                o.w = tanhf(__uint_as_float(d[j + 3]) + bs[cb + cc * 32 + j + 3]);
                *reinterpret_cast<float4*>(orow + j) = o;
            }
        }
    } else {
        // Transposed coalesced epilogue: two passes over 256-col groups.
        float* rs = reinterpret_cast<float*>(smem + STAGES0);   // 128 x 257 floats
        const int pb = (m0 + 128 * (int)rank) >> 1;             // 64 p-rows
        #pragma unroll 1
        for (int cp = 0; cp < 2; cp++) {
            if (cg == cp) {
                const int vl = sub * 32 + lane;                  // 0..127
                #pragma unroll 1
                for (int cc = 0; cc < 8; cc++) {
                    uint32_t d[32];
                    TCG_LD_X32(d, tmem + cp * 256 + cc * 32);
                    TCG_WAIT_LD();
                    #pragma unroll
                    for (int j = 0; j < 32; j++)
                        rs[vl * 257 + cc * 32 + j] = __uint_as_float(d[j]);
                }
            }
            __syncthreads();
            #pragma unroll 1
            for (int r8 = 0; r8 < 8; r8++) {
                const int pr = wid * 8 + r8;                     // 0..63
                const float* hrow = aux + (size_t)(pb + pr) * CHANNELS + n0 + 256 * cp;
                float* orow = outp + (size_t)(pb + pr) * 2048 + 2 * (size_t)(n0 + 256 * cp);
                const float* r0 = rs + (2 * pr) * 257;
                const float* r1 = r0 + 257;
                #pragma unroll
                for (int c = 0; c < 4; c++) {
                    const int i0 = 64 * c + 2 * lane;
                    float2 hv = *reinterpret_cast<const float2*>(hrow + i0);
                    float g0 = 1.f - hv.x * hv.x;
                    float g1 = 1.f - hv.y * hv.y;
                    float4 o;
                    o.x = g0 * r0[i0];
                    o.y = g0 * r1[i0];
                    o.z = g1 * r0[i0 + 1];
                    o.w = g1 * r1[i0 + 1];
                    *reinterpret_cast<float4*>(orow + 4 * (32 * c + lane)) = o;
                }
            }
            __syncthreads();
        }
    }

    TCG_FENCE_BEFORE();
    __syncthreads();
    CLUSTER_SYNC();   // all cg2-TMA completions / MC commits have landed
    if (tid == 0) {
        #pragma unroll
        for (int s = 0; s < ST; s++) { MBAR_INVAL(sbase + 16 + 8 * s); MBAR_INVAL(sbase + 48 + 8 * s); }
        MBAR_INVAL(sbase + 80);
    }
    __syncthreads();
    if (wid == 7) { TCG_RELINQ_CG2(); TCG_DEALLOC_CG2(tmem, 512); }
    CLUSTER_SYNC();

#else  // ---------- non-sm_103a fallback (never runs on GB300) ----------
    const int tid = threadIdx.x;
    const int rank = (int)(blockIdx.x & 1);
    const int n0 = (int)(blockIdx.x >> 1) * BN2;
    const int m0 = blockIdx.y * BMP + 128 * rank;
    for (int idx = tid; idx < 128 * BN2; idx += blockDim.x) {
        int mi = idx >> 9, ni = idx & 511;
        int m = m0 + mi, n = n0 + ni;
        float acc = 0.f;
        for (int k = 0; k < CHANNELS; k++)
            acc += __half2float(Araw[(size_t)m * CHANNELS + k]) *
                   __half2float(Wraw[(size_t)n * CHANNELS + k]);
        if (EPI == 0) {
            outp[(size_t)m * CHANNELS + n] = tanhf(acc + aux[n]);
        } else {
            int p = m >> 1, kb = m & 1;
            float hv = aux[(size_t)p * CHANNELS + n];
            outp[(size_t)p * 2048 + 2 * (size_t)n + kb] = (1.f - hv * hv) * acc;
        }
    }
#endif
}

// ---------------- host launcher ----------------
typedef CUresult (*tmap_encode_fn)(
    CUtensorMap*, CUtensorMapDataType, cuuint32_t, void*,
    const cuuint64_t*, const cuuint64_t*, const cuuint32_t*, const cuuint32_t*,
    CUtensorMapInterleave, CUtensorMapSwizzle, CUtensorMapL2promotion,
    CUtensorMapFloatOOBfill);

static void make_map2d(tmap_encode_fn enc, CUtensorMap* m, void* base,
                       unsigned long long rows) {
    cuuint64_t dims[2]    = {(cuuint64_t)CHANNELS, (cuuint64_t)rows};
    cuuint64_t strides[1] = {(cuuint64_t)(CHANNELS * sizeof(__half))};
    cuuint32_t box[2]     = {64u, 128u};
    cuuint32_t es[2]      = {1u, 1u};
    enc(m, CU_TENSOR_MAP_DATA_TYPE_FLOAT16, 2, base, dims, strides, box, es,
        CU_TENSOR_MAP_INTERLEAVE_NONE, CU_TENSOR_MAP_SWIZZLE_128B,
        CU_TENSOR_MAP_L2_PROMOTION_L2_128B, CU_TENSOR_MAP_FLOAT_OOB_FILL_NONE);
}

extern "C" void kernel_launch(void* const* d_in, const int* in_sizes, int n_in,
                              void* d_out, int out_size)
{
    const float* x = (const float*)d_in[0];   // [3*PIVOT, CHANNELS]
    const float* W = (const float*)d_in[1];   // [CHANNELS, CHANNELS]
    const float* b = (const float*)d_in[2];   // [CHANNELS]
    float* out = (float*)d_out;

    void *pX = nullptr, *pW = nullptr, *pA2 = nullptr;
    cudaGetSymbolAddress(&pX,  Xh_g);
    cudaGetSymbolAddress(&pW,  Wh_g);
    cudaGetSymbolAddress(&pA2, A2_g);

    void* encp = nullptr;
    cudaDriverEntryPointQueryResult qr;
    cudaGetDriverEntryPoint("cuTensorMapEncodeTiled", &encp, cudaEnableDefault, &qr);
    tmap_encode_fn enc = (tmap_encode_fn)encp;

    CUtensorMap mX, mW, mA2;
    make_map2d(enc, &mX,  pX,  PIVOT);
    make_map2d(enc, &mW,  pW,  CHANNELS);
    make_map2d(enc, &mA2, pA2, 2 * PIVOT);

    cudaFuncSetAttribute(gemm_cg2<0>, cudaFuncAttributeMaxDynamicSharedMemorySize, SMEM_TOTAL);
    cudaFuncSetAttribute(gemm_cg2<1>, cudaFuncAttributeMaxDynamicSharedMemorySize, SMEM_TOTAL);

    const size_t NX = (size_t)PIVOT * CHANNELS / 4;
    const size_t NW = (size_t)CHANNELS * CHANNELS / 4;
    cvt_XW<<<(unsigned)((NX + NW) / 256), 256>>>(x, W);
    cvt_J<<<(unsigned)((size_t)PIVOT * 512 / 256), 256>>>(x + (size_t)PIVOT * CHANNELS);

    // gridx = 2 n-tiles x 2 ranks = 4
    dim3 g1(4, PIVOT / BMP);                 // (4, 64)  = 256 CTAs (128 pairs)
    gemm_cg2<0><<<g1, 256, SMEM_TOTAL>>>(mX, mW, (const __half*)pX, (const __half*)pW, b, out);

    dim3 g2(4, (2 * PIVOT) / BMP);           // (4, 128) = 512 CTAs (256 pairs)
    gemm_cg2<1><<<g2, 256, SMEM_TOTAL>>>(mA2, mW, (const __half*)pA2, (const __half*)pW,
                                         out, out + (size_t)PIVOT * CHANNELS);
}